// round 16
// baseline (speedup 1.0000x reference)
#include <cuda_runtime.h>
#include <math_constants.h>
#include <cstdint>

// feature_matrix_batch: [S=2, N=32, I=4096, D=128] f32
// cluster_index:        [S, N*I] int32 or int64, values in [n*K,(n+1)*K)
// output:               [S, N, K=16, D=128] f32 segment max (-inf identity)

#define SS       2
#define NN       32
#define II       4096
#define DD       128
#define KK       16
#define CHUNKS   4
#define PTS      (II / CHUNKS)         // 1024 points per block
#define NBLK     (SS * NN * CHUNKS)    // 256 blocks
#define ROWF4    32                    // float4 per point-row
#define TILE     (KK * ROWF4)          // 512 float4 per block partial

#define STAGES      3
#define SPTS        64                          // points per stage
#define STAGE_BYTES (SPTS * DD * 4)             // 32 KB
#define NSTEP       (PTS / SPTS)                // 16 stages per block
#define NTHREADS    288                         // 8 consumer warps + 1 producer
#define NCONS       256                         // consumer threads

// smem layout (dynamic)
#define SM_BUF    0
#define SM_PLIST  (STAGES * STAGE_BYTES)        // u16[1024]  -> 2048 B
#define SM_KARR   (SM_PLIST + 2048)             // u8[1024]
#define SM_OFF    (SM_KARR + 1024)              // int[129]   -> 516 B
#define SM_CUR    (SM_OFF + 520)                // int[128]
#define SM_BAR    (SM_CUR + 512)                // 6 mbarriers (8 B each)
#define SM_TOTAL  (SM_BAR + 6 * 8)

// Per-block partials: [256][512 f4] = 2 MB, plus per-cloud arrival counters.
__device__ float4 g_scratch4[NBLK * TILE];
__device__ int    g_count[SS * NN];   // zero-init; reset by reducer each run

static __device__ __forceinline__ float4 vmax4(float4 a, float4 b) {
    a.x = fmaxf(a.x, b.x);
    a.y = fmaxf(a.y, b.y);
    a.z = fmaxf(a.z, b.z);
    a.w = fmaxf(a.w, b.w);
    return a;
}

static __device__ __forceinline__ uint32_t smem_u32(const void* p) {
    return (uint32_t)__cvta_generic_to_shared(p);
}

#define MBAR_INIT(addr, cnt) \
    asm volatile("mbarrier.init.shared.b64 [%0], %1;" :: "r"(addr), "r"(cnt) : "memory")
#define MBAR_EXPECT_TX(addr, tx) \
    asm volatile("mbarrier.arrive.expect_tx.shared.b64 _, [%0], %1;" :: "r"(addr), "r"(tx) : "memory")
#define MBAR_ARRIVE(addr) \
    asm volatile("mbarrier.arrive.shared.b64 _, [%0];" :: "r"(addr) : "memory")
#define MBAR_WAIT(addr, parity) do {                                          \
    asm volatile(                                                             \
        "{\n\t.reg .pred P1;\n\t"                                             \
        "WAIT_LOOP_%=:\n\t"                                                   \
        "mbarrier.try_wait.parity.acquire.cta.shared::cta.b64 P1, [%0], %1;\n\t" \
        "@P1 bra.uni WAIT_DONE_%=;\n\t"                                       \
        "bra.uni WAIT_LOOP_%=;\n\t"                                           \
        "WAIT_DONE_%=:\n\t}"                                                  \
        :: "r"(addr), "r"(parity) : "memory");                                \
} while (0)
#define BULK_CP(dst, src, bytes, bar) \
    asm volatile("cp.async.bulk.shared::cluster.global.mbarrier::complete_tx::bytes " \
                 "[%0], [%1], %2, [%3];" \
                 :: "r"(dst), "l"(src), "r"(bytes), "r"(bar) : "memory")
#define BAR_CONS() \
    asm volatile("bar.sync 1, %0;" :: "r"(NCONS) : "memory")

__global__ void __launch_bounds__(NTHREADS) maxpool_fused(
    const float4* __restrict__ f4,
    const int*    __restrict__ cw,     // raw 32-bit view of cluster_index
    float4*       __restrict__ out4)
{
    extern __shared__ __align__(1024) char smem[];
    unsigned short* plist = (unsigned short*)(smem + SM_PLIST);
    unsigned char*  karr  = (unsigned char*)(smem + SM_KARR);
    int*            off   = (int*)(smem + SM_OFF);   // 129 entries
    int*            cur   = (int*)(smem + SM_CUR);   // 128 cursors
    const uint32_t  bar0  = smem_u32(smem + SM_BAR);
    // full[s] = bar0 + 8*s ; empty[s] = bar0 + 8*(STAGES+s)

    const int b     = blockIdx.x;
    const int chunk = b & (CHUNKS - 1);
    const int cloud = b >> 2;                 // CHUNKS == 4
    const int n     = cloud & (NN - 1);
    const int x     = threadIdx.x;
    const int w     = x >> 5;
    const int lane  = x & 31;

    __shared__ int s_last;

    if (x == 0) {
        #pragma unroll
        for (int s = 0; s < STAGES; s++) {
            MBAR_INIT(bar0 + 8 * s, 1);                  // full: producer arrive
            MBAR_INIT(bar0 + 8 * (STAGES + s), 8);       // empty: 8 consumer warps
        }
    }
    __syncthreads();   // barriers visible to everyone

    const char* gsrc =
        (const char*)(f4 + ((size_t)cloud * II + (size_t)chunk * PTS) * ROWF4);

    if (w == 8) {
        // ---------------- producer: starts streaming immediately ----------
        if (lane == 0) {
            int s = 0, pe = 1;
            for (int g = 0; g < NSTEP; g++) {
                MBAR_WAIT(bar0 + 8 * (STAGES + s), pe);
                MBAR_EXPECT_TX(bar0 + 8 * s, STAGE_BYTES);
                BULK_CP(smem_u32(smem) + s * STAGE_BYTES,
                        (const void*)(gsrc + (size_t)g * STAGE_BYTES),
                        STAGE_BYTES, bar0 + 8 * s);
                if (++s == STAGES) { s = 0; pe ^= 1; }
            }
        }
    } else {
        // ------- consumers: counting-sort points, then stream-reduce -------
        // dtype sniff: indices < 512 -> int64 high (odd) words all zero.
        const bool is64 =
            ((cw[1] | cw[3] | cw[5] | cw[7] | cw[9] | cw[11] | cw[13] | cw[15]) == 0);

        for (int i = x; i < 128; i += NCONS) cur[i] = 0;
        BAR_CONS();

        // histogram over buckets (stage, owner-warp)
        const size_t idx_base = (size_t)cloud * II + (size_t)chunk * PTS;
        for (int j = x; j < PTS; j += NCONS) {
            int k = (is64 ? cw[2 * (idx_base + j)] : cw[idx_base + j]) - n * KK;
            karr[j] = (unsigned char)k;
            if ((unsigned)k < (unsigned)KK)
                atomicAdd(&cur[(j >> 6) * 8 + (k >> 1)], 1);
        }
        BAR_CONS();

        if (x == 0) {                    // exclusive prefix over 128 buckets
            int acc = 0;
            #pragma unroll
            for (int t = 0; t < 128; t++) {
                const int c = cur[t];
                off[t] = acc;
                cur[t] = acc;
                acc += c;
            }
            off[128] = acc;
        }
        BAR_CONS();

        for (int j = x; j < PTS; j += NCONS) {      // scatter
            const int k = karr[j];
            if ((unsigned)k < (unsigned)KK) {
                const int p = atomicAdd(&cur[(j >> 6) * 8 + (k >> 1)], 1);
                plist[p] = (unsigned short)((j & 63) | ((k & 1) << 8));
            }
        }
        BAR_CONS();

        // ---- stream-reduce: warp w owns segments 2w, 2w+1 ----
        const float4 neg4 = make_float4(-CUDART_INF_F, -CUDART_INF_F,
                                        -CUDART_INF_F, -CUDART_INF_F);
        float4 acc0 = neg4, acc1 = neg4;

        int s = 0, pf = 0;
        for (int g = 0; g < NSTEP; g++) {
            MBAR_WAIT(bar0 + 8 * s, pf);

            const int lo = off[g * 8 + w];
            const int hi = off[g * 8 + w + 1];
            const float4* rows = (const float4*)(smem + SM_BUF
                                                 + (size_t)s * STAGE_BYTES);
            int i = lo;
            for (; i + 2 <= hi; i += 2) {
                const int e0 = plist[i + 0];            // broadcast LDS
                const int e1 = plist[i + 1];
                const float4 v0 = rows[(e0 & 63) * ROWF4 + lane];  // LDS.128
                const float4 v1 = rows[(e1 & 63) * ROWF4 + lane];
                if (e0 & 256) acc1 = vmax4(acc1, v0); else acc0 = vmax4(acc0, v0);
                if (e1 & 256) acc1 = vmax4(acc1, v1); else acc0 = vmax4(acc0, v1);
            }
            if (i < hi) {
                const int e = plist[i];
                const float4 v = rows[(e & 63) * ROWF4 + lane];
                if (e & 256) acc1 = vmax4(acc1, v); else acc0 = vmax4(acc0, v);
            }
            __syncwarp();
            if (lane == 0) MBAR_ARRIVE(bar0 + 8 * (STAGES + s));
            if (++s == STAGES) { s = 0; pf ^= 1; }
        }

        // exclusive writes: no merge needed
        float4* dst = g_scratch4 + (size_t)b * TILE;
        dst[(2 * w + 0) * ROWF4 + lane] = acc0;
        dst[(2 * w + 1) * ROWF4 + lane] = acc1;
    }

    // ---- last block of each cloud reduces its 4 partials to out ----
    __threadfence();
    __syncthreads();
    if (x == 0)
        s_last = (atomicAdd(&g_count[cloud], 1) == CHUNKS - 1);
    __syncthreads();

    if (s_last) {
        __threadfence();   // acquire-side: order partial reads after counter
        const float4* base = g_scratch4 + (size_t)cloud * CHUNKS * TILE;
        float4*       dout = out4 + (size_t)cloud * TILE;
        for (int idx = x; idx < TILE; idx += NTHREADS) {
            float4 mv = base[idx];
            #pragma unroll
            for (int c = 1; c < CHUNKS; c++)
                mv = vmax4(mv, base[(size_t)c * TILE + idx]);
            dout[idx] = mv;
        }
        if (x == 0) g_count[cloud] = 0;   // rearm for next graph replay
    }
}

extern "C" void kernel_launch(void* const* d_in, const int* in_sizes, int n_in,
                              void* d_out, int out_size)
{
    const float4* f4  = (const float4*)d_in[0];
    const int*    cw  = (const int*)d_in[1];
    float4*       out = (float4*)d_out;

    static bool attr_done = false;
    if (!attr_done) {
        cudaFuncSetAttribute(maxpool_fused,
                             cudaFuncAttributeMaxDynamicSharedMemorySize, SM_TOTAL);
        attr_done = true;
    }
    maxpool_fused<<<NBLK, NTHREADS, SM_TOTAL>>>(f4, cw, out);
}

// round 17
// speedup vs baseline: 1.0174x; 1.0174x over previous
#include <cuda_runtime.h>
#include <math_constants.h>
#include <cstdint>

// feature_matrix_batch: [S=2, N=32, I=4096, D=128] f32
// cluster_index:        [S, N*I] int32 or int64, values in [n*K,(n+1)*K)
// output:               [S, N, K=16, D=128] f32 segment max (-inf identity)

#define SS       2
#define NN       32
#define II       4096
#define DD       128
#define KK       16
#define CHUNKS   4
#define PTS      (II / CHUNKS)         // 1024 points per block
#define NBLK     (SS * NN * CHUNKS)    // 256 blocks
#define ROWF4    32                    // float4 per point-row
#define TILE     (KK * ROWF4)          // 512 float4 per block partial

#define STAGES      3
#define SPTS        64                          // points per stage
#define STAGE_BYTES (SPTS * DD * 4)             // 32 KB
#define NSTEP       (PTS / SPTS)                // 16 stages per block
#define NTHREADS    288                         // 8 consumer warps + 1 producer
#define NCONS       256                         // consumer threads

// smem layout (dynamic)
#define SM_BUF    0
#define SM_PLIST  (STAGES * STAGE_BYTES)        // u16[1024]  -> 2048 B
#define SM_KARR   (SM_PLIST + 2048)             // u8[1024]
#define SM_OFF    (SM_KARR + 1024)              // int[129]   -> 516 B
#define SM_CUR    (SM_OFF + 520)                // int[128]
#define SM_BAR    (SM_CUR + 512)                // 6 mbarriers (8 B each)
#define SM_TOTAL  (SM_BAR + 6 * 8)

// Per-block partials: [256][512 f4] = 2 MB, plus per-cloud arrival counters.
__device__ float4 g_scratch4[NBLK * TILE];
__device__ int    g_count[SS * NN];   // zero-init; reset by reducer each run

static __device__ __forceinline__ float4 vmax4(float4 a, float4 b) {
    a.x = fmaxf(a.x, b.x);
    a.y = fmaxf(a.y, b.y);
    a.z = fmaxf(a.z, b.z);
    a.w = fmaxf(a.w, b.w);
    return a;
}

static __device__ __forceinline__ uint32_t smem_u32(const void* p) {
    return (uint32_t)__cvta_generic_to_shared(p);
}

#define MBAR_INIT(addr, cnt) \
    asm volatile("mbarrier.init.shared.b64 [%0], %1;" :: "r"(addr), "r"(cnt) : "memory")
#define MBAR_EXPECT_TX(addr, tx) \
    asm volatile("mbarrier.arrive.expect_tx.shared.b64 _, [%0], %1;" :: "r"(addr), "r"(tx) : "memory")
#define MBAR_ARRIVE(addr) \
    asm volatile("mbarrier.arrive.shared.b64 _, [%0];" :: "r"(addr) : "memory")
#define MBAR_WAIT(addr, parity) do {                                          \
    asm volatile(                                                             \
        "{\n\t.reg .pred P1;\n\t"                                             \
        "WAIT_LOOP_%=:\n\t"                                                   \
        "mbarrier.try_wait.parity.acquire.cta.shared::cta.b64 P1, [%0], %1;\n\t" \
        "@P1 bra.uni WAIT_DONE_%=;\n\t"                                       \
        "bra.uni WAIT_LOOP_%=;\n\t"                                           \
        "WAIT_DONE_%=:\n\t}"                                                  \
        :: "r"(addr), "r"(parity) : "memory");                                \
} while (0)
#define BULK_CP(dst, src, bytes, bar) \
    asm volatile("cp.async.bulk.shared::cluster.global.mbarrier::complete_tx::bytes " \
                 "[%0], [%1], %2, [%3];" \
                 :: "r"(dst), "l"(src), "r"(bytes), "r"(bar) : "memory")
#define BAR_CONS() \
    asm volatile("bar.sync 1, %0;" :: "r"(NCONS) : "memory")

__global__ void __launch_bounds__(NTHREADS) maxpool_fused(
    const float4* __restrict__ f4,
    const int*    __restrict__ cw,     // raw 32-bit view of cluster_index
    float4*       __restrict__ out4)
{
    extern __shared__ __align__(1024) char smem[];
    unsigned short* plist = (unsigned short*)(smem + SM_PLIST);
    unsigned char*  karr  = (unsigned char*)(smem + SM_KARR);
    int*            off   = (int*)(smem + SM_OFF);   // 129 entries
    int*            cur   = (int*)(smem + SM_CUR);   // 128 cursors
    const uint32_t  bar0  = smem_u32(smem + SM_BAR);
    // full[s] = bar0 + 8*s ; empty[s] = bar0 + 8*(STAGES+s)

    const int b     = blockIdx.x;
    const int chunk = b & (CHUNKS - 1);
    const int cloud = b >> 2;                 // CHUNKS == 4
    const int n     = cloud & (NN - 1);
    const int x     = threadIdx.x;
    const int w     = x >> 5;
    const int lane  = x & 31;

    __shared__ int s_last;

    if (x == 0) {
        #pragma unroll
        for (int s = 0; s < STAGES; s++) {
            MBAR_INIT(bar0 + 8 * s, 1);                  // full: producer arrive
            MBAR_INIT(bar0 + 8 * (STAGES + s), 8);       // empty: 8 consumer warps
        }
    }
    __syncthreads();   // barriers visible to everyone

    const char* gsrc =
        (const char*)(f4 + ((size_t)cloud * II + (size_t)chunk * PTS) * ROWF4);

    if (w == 8) {
        // ---------------- producer: starts streaming immediately ----------
        if (lane == 0) {
            int s = 0, pe = 1;
            for (int g = 0; g < NSTEP; g++) {
                MBAR_WAIT(bar0 + 8 * (STAGES + s), pe);
                MBAR_EXPECT_TX(bar0 + 8 * s, STAGE_BYTES);
                BULK_CP(smem_u32(smem) + s * STAGE_BYTES,
                        (const void*)(gsrc + (size_t)g * STAGE_BYTES),
                        STAGE_BYTES, bar0 + 8 * s);
                if (++s == STAGES) { s = 0; pe ^= 1; }
            }
        }
    } else {
        // ------- consumers: counting-sort points, then stream-reduce -------
        // dtype sniff: indices < 512 -> int64 high (odd) words all zero.
        const bool is64 =
            ((cw[1] | cw[3] | cw[5] | cw[7] | cw[9] | cw[11] | cw[13] | cw[15]) == 0);

        for (int i = x; i < 128; i += NCONS) cur[i] = 0;
        BAR_CONS();

        // histogram over buckets (stage, owner-warp)
        const size_t idx_base = (size_t)cloud * II + (size_t)chunk * PTS;
        for (int j = x; j < PTS; j += NCONS) {
            int k = (is64 ? cw[2 * (idx_base + j)] : cw[idx_base + j]) - n * KK;
            karr[j] = (unsigned char)k;
            if ((unsigned)k < (unsigned)KK)
                atomicAdd(&cur[(j >> 6) * 8 + (k >> 1)], 1);
        }
        BAR_CONS();

        if (x == 0) {                    // exclusive prefix over 128 buckets
            int acc = 0;
            #pragma unroll
            for (int t = 0; t < 128; t++) {
                const int c = cur[t];
                off[t] = acc;
                cur[t] = acc;
                acc += c;
            }
            off[128] = acc;
        }
        BAR_CONS();

        for (int j = x; j < PTS; j += NCONS) {      // scatter
            const int k = karr[j];
            if ((unsigned)k < (unsigned)KK) {
                const int p = atomicAdd(&cur[(j >> 6) * 8 + (k >> 1)], 1);
                plist[p] = (unsigned short)((j & 63) | ((k & 1) << 8));
            }
        }
        BAR_CONS();

        // ---- stream-reduce: warp w owns segments 2w, 2w+1 ----
        const float4 neg4 = make_float4(-CUDART_INF_F, -CUDART_INF_F,
                                        -CUDART_INF_F, -CUDART_INF_F);
        float4 acc0 = neg4, acc1 = neg4;

        int s = 0, pf = 0;
        for (int g = 0; g < NSTEP; g++) {
            MBAR_WAIT(bar0 + 8 * s, pf);

            const int lo = off[g * 8 + w];
            const int hi = off[g * 8 + w + 1];
            const float4* rows = (const float4*)(smem + SM_BUF
                                                 + (size_t)s * STAGE_BYTES);
            int i = lo;
            for (; i + 2 <= hi; i += 2) {
                const int e0 = plist[i + 0];            // broadcast LDS
                const int e1 = plist[i + 1];
                const float4 v0 = rows[(e0 & 63) * ROWF4 + lane];  // LDS.128
                const float4 v1 = rows[(e1 & 63) * ROWF4 + lane];
                if (e0 & 256) acc1 = vmax4(acc1, v0); else acc0 = vmax4(acc0, v0);
                if (e1 & 256) acc1 = vmax4(acc1, v1); else acc0 = vmax4(acc0, v1);
            }
            if (i < hi) {
                const int e = plist[i];
                const float4 v = rows[(e & 63) * ROWF4 + lane];
                if (e & 256) acc1 = vmax4(acc1, v); else acc0 = vmax4(acc0, v);
            }
            __syncwarp();
            if (lane == 0) MBAR_ARRIVE(bar0 + 8 * (STAGES + s));
            if (++s == STAGES) { s = 0; pf ^= 1; }
        }

        // exclusive writes: no merge needed
        float4* dst = g_scratch4 + (size_t)b * TILE;
        dst[(2 * w + 0) * ROWF4 + lane] = acc0;
        dst[(2 * w + 1) * ROWF4 + lane] = acc1;
    }

    // ---- last block of each cloud reduces its 4 partials to out ----
    __threadfence();
    __syncthreads();
    if (x == 0)
        s_last = (atomicAdd(&g_count[cloud], 1) == CHUNKS - 1);
    __syncthreads();

    if (s_last) {
        __threadfence();   // acquire-side: order partial reads after counter
        const float4* base = g_scratch4 + (size_t)cloud * CHUNKS * TILE;
        float4*       dout = out4 + (size_t)cloud * TILE;
        for (int idx = x; idx < TILE; idx += NTHREADS) {
            float4 mv = base[idx];
            #pragma unroll
            for (int c = 1; c < CHUNKS; c++)
                mv = vmax4(mv, base[(size_t)c * TILE + idx]);
            dout[idx] = mv;
        }
        if (x == 0) g_count[cloud] = 0;   // rearm for next graph replay
    }
}

extern "C" void kernel_launch(void* const* d_in, const int* in_sizes, int n_in,
                              void* d_out, int out_size)
{
    const float4* f4  = (const float4*)d_in[0];
    const int*    cw  = (const int*)d_in[1];
    float4*       out = (float4*)d_out;

    static bool attr_done = false;
    if (!attr_done) {
        cudaFuncSetAttribute(maxpool_fused,
                             cudaFuncAttributeMaxDynamicSharedMemorySize, SM_TOTAL);
        attr_done = true;
    }
    maxpool_fused<<<NBLK, NTHREADS, SM_TOTAL>>>(f4, cw, out);
}